// round 9
// baseline (speedup 1.0000x reference)
#include <cuda_runtime.h>
#include <cfloat>

// Problem shape (fixed by reference): point_cloud [32, 262144, 3] fp32
static constexpr int NB       = 32;
static constexpr int NPTS     = 262144;
static constexpr int F_PER_B  = NPTS * 3;            // 786432 floats per batch
static constexpr int Q_PER_B  = F_PER_B / 4;         // 196608 float4 per batch

static constexpr int THREADS  = 256;
static constexpr int M1       = 32;                  // minmax blocks per batch
static constexpr int M2       = 64;                  // voxel blocks per batch
static constexpr int PER_B    = M1 + M2;             // 96 blocks per batch
static constexpr int CHUNK1   = Q_PER_B / M1;        // 6144 float4/block
static constexpr int ITER1    = CHUNK1 / (3 * THREADS);  // 8
static constexpr int CHUNK2   = Q_PER_B / M2;        // 3072 float4/block
static constexpr int ITER2    = CHUNK2 / (3 * THREADS);  // 4

// Persistent state — all zero-initialized; the last voxel block of each batch
// resets that batch's counters at the end of every launch -> graph-replay safe.
__device__ float    g_part[NB][6][M1];   // partials: 0..2 min(x,y,z), 3..5 max
__device__ unsigned g_done[NB];          // completed minmax blocks per batch
__device__ unsigned g_vdone[NB];         // completed voxel blocks per batch

// Component bookkeeping: float4 at index idx has components
// ((idx)%3,(idx+1)%3,(idx+2)%3,(idx)%3). All block bases are multiples of 3
// and the iteration stride THREADS=256 ≡ 1 (mod 3), so with r = tid%3 the
// float4 at unrolled sub-iter u has leading component (r+u)%3. All selection
// is static after pre-rotating constants/accumulators by r.

__global__ void __launch_bounds__(THREADS)
fused_pipeline_kernel(const float4* __restrict__ p, float4* __restrict__ out) {
    const int b   = blockIdx.x / PER_B;
    const int s   = blockIdx.x % PER_B;
    const int tid = threadIdx.x;
    const int r   = tid % 3;

    if (s < M1) {
        // ───────────── Producer: min/max partials for batch b ─────────────
        const float4* pb = p + (size_t)b * Q_PER_B + s * CHUNK1;

        float mnA0 =  FLT_MAX, mnA1 =  FLT_MAX, mnA2 =  FLT_MAX;
        float mxA0 = -FLT_MAX, mxA1 = -FLT_MAX, mxA2 = -FLT_MAX;

        #pragma unroll 4
        for (int ko = 0; ko < ITER1; ko++) {
            const float4 a = pb[(ko * 3 + 0) * THREADS + tid];  // default policy: fills L2 for the consumer
            const float4 d = pb[(ko * 3 + 1) * THREADS + tid];
            const float4 c = pb[(ko * 3 + 2) * THREADS + tid];
            // u=0: comps (A0,A1,A2,A0)
            mnA0 = fminf(mnA0, fminf(a.x, a.w)); mxA0 = fmaxf(mxA0, fmaxf(a.x, a.w));
            mnA1 = fminf(mnA1, a.y);             mxA1 = fmaxf(mxA1, a.y);
            mnA2 = fminf(mnA2, a.z);             mxA2 = fmaxf(mxA2, a.z);
            // u=1: comps (A1,A2,A0,A1)
            mnA1 = fminf(mnA1, fminf(d.x, d.w)); mxA1 = fmaxf(mxA1, fmaxf(d.x, d.w));
            mnA2 = fminf(mnA2, d.y);             mxA2 = fmaxf(mxA2, d.y);
            mnA0 = fminf(mnA0, d.z);             mxA0 = fmaxf(mxA0, d.z);
            // u=2: comps (A2,A0,A1,A2)
            mnA2 = fminf(mnA2, fminf(c.x, c.w)); mxA2 = fmaxf(mxA2, fmaxf(c.x, c.w));
            mnA0 = fminf(mnA0, c.y);             mxA0 = fmaxf(mxA0, c.y);
            mnA1 = fminf(mnA1, c.z);             mxA1 = fmaxf(mxA1, c.z);
        }

        // Un-rotate: comp k lives in slot (k - r + 3) % 3
        float mn0, mn1, mn2, mx0, mx1, mx2;
        if (r == 0)      { mn0 = mnA0; mn1 = mnA1; mn2 = mnA2; mx0 = mxA0; mx1 = mxA1; mx2 = mxA2; }
        else if (r == 1) { mn0 = mnA2; mn1 = mnA0; mn2 = mnA1; mx0 = mxA2; mx1 = mxA0; mx2 = mxA1; }
        else             { mn0 = mnA1; mn1 = mnA2; mn2 = mnA0; mx0 = mxA1; mx1 = mxA2; mx2 = mxA0; }

        #pragma unroll
        for (int off = 16; off > 0; off >>= 1) {
            mn0 = fminf(mn0, __shfl_xor_sync(0xFFFFFFFFu, mn0, off));
            mn1 = fminf(mn1, __shfl_xor_sync(0xFFFFFFFFu, mn1, off));
            mn2 = fminf(mn2, __shfl_xor_sync(0xFFFFFFFFu, mn2, off));
            mx0 = fmaxf(mx0, __shfl_xor_sync(0xFFFFFFFFu, mx0, off));
            mx1 = fmaxf(mx1, __shfl_xor_sync(0xFFFFFFFFu, mx1, off));
            mx2 = fmaxf(mx2, __shfl_xor_sync(0xFFFFFFFFu, mx2, off));
        }

        __shared__ float sh[6][THREADS / 32];
        const int w = tid >> 5, lane = tid & 31;
        if (lane == 0) {
            sh[0][w] = mn0; sh[1][w] = mn1; sh[2][w] = mn2;
            sh[3][w] = mx0; sh[4][w] = mx1; sh[5][w] = mx2;
        }
        __syncthreads();

        if (tid < 6) {
            float v = sh[tid][0];
            if (tid < 3) {
                #pragma unroll
                for (int k = 1; k < THREADS / 32; k++) v = fminf(v, sh[tid][k]);
            } else {
                #pragma unroll
                for (int k = 1; k < THREADS / 32; k++) v = fmaxf(v, sh[tid][k]);
            }
            g_part[b][tid][s] = v;
        }
        __syncthreads();
        if (tid == 0) {
            __threadfence();                       // publish partials before signal
            atomicAdd(&g_done[b], 1u);             // release
        }
    } else {
        // ───────────── Consumer: voxelize chunk (s-M1) of batch b ──────────
        const int c2 = s - M1;

        // Spin until all M1 producer blocks for this batch have signalled.
        if (tid == 0) {
            while (__ldcg((const unsigned*)&g_done[b]) < (unsigned)M1)
                __nanosleep(64);
            __threadfence();                       // acquire
        }
        __syncthreads();

        // Reduce the 32 partials: warps 0..5, one quantity each (L2 reads).
        __shared__ float cst[6];
        {
            const int w = tid >> 5, lane = tid & 31;
            if (w < 6) {
                float v = __ldcg(&g_part[b][w][lane]);
                if (w < 3) {
                    #pragma unroll
                    for (int off = 16; off > 0; off >>= 1)
                        v = fminf(v, __shfl_xor_sync(0xFFFFFFFFu, v, off));
                } else {
                    #pragma unroll
                    for (int off = 16; off > 0; off >>= 1)
                        v = fmaxf(v, __shfl_xor_sync(0xFFFFFFFFu, v, off));
                }
                if (lane == 0) cst[w] = v;
            }
        }
        __syncthreads();

        // Same RN /40 as reference, then reciprocal-multiply per point.
        const float mnc[3]  = { cst[0], cst[1], cst[2] };
        const float invc[3] = { 1.0f / ((cst[3] - cst[0]) / 40.0f),
                                1.0f / ((cst[4] - cst[1]) / 40.0f),
                                1.0f / ((cst[5] - cst[2]) / 40.0f) };
        const float mn_0 = mnc[r], mn_1 = mnc[(r + 1) % 3], mn_2 = mnc[(r + 2) % 3];
        const float iv_0 = invc[r], iv_1 = invc[(r + 1) % 3], iv_2 = invc[(r + 2) % 3];

        const size_t base = (size_t)b * Q_PER_B + (size_t)c2 * CHUNK2;
        const float4* pb = p + base;
        float4* ob = out + base;

        // Double-buffered main loop (~6 LDG.128 in flight/thread).
        float4 a = __ldcs(&pb[0 * THREADS + tid]);   // expect L2-hot (producer just read it)
        float4 d = __ldcs(&pb[1 * THREADS + tid]);
        float4 c = __ldcs(&pb[2 * THREADS + tid]);

        #pragma unroll
        for (int ko = 0; ko < ITER2; ko++) {
            float4 an, dn, cn;
            if (ko + 1 < ITER2) {
                an = __ldcs(&pb[((ko + 1) * 3 + 0) * THREADS + tid]);
                dn = __ldcs(&pb[((ko + 1) * 3 + 1) * THREADS + tid]);
                cn = __ldcs(&pb[((ko + 1) * 3 + 2) * THREADS + tid]);
            }

            float4 ra, rd, rc;
            // u=0: comps (0,1,2,0) after rotation
            ra.x = floorf((a.x - mn_0) * iv_0);
            ra.y = floorf((a.y - mn_1) * iv_1);
            ra.z = floorf((a.z - mn_2) * iv_2);
            ra.w = floorf((a.w - mn_0) * iv_0);
            // u=1: comps (1,2,0,1)
            rd.x = floorf((d.x - mn_1) * iv_1);
            rd.y = floorf((d.y - mn_2) * iv_2);
            rd.z = floorf((d.z - mn_0) * iv_0);
            rd.w = floorf((d.w - mn_1) * iv_1);
            // u=2: comps (2,0,1,2)
            rc.x = floorf((c.x - mn_2) * iv_2);
            rc.y = floorf((c.y - mn_0) * iv_0);
            rc.z = floorf((c.z - mn_1) * iv_1);
            rc.w = floorf((c.w - mn_2) * iv_2);

            __stcs(&ob[(ko * 3 + 0) * THREADS + tid], ra);
            __stcs(&ob[(ko * 3 + 1) * THREADS + tid], rd);
            __stcs(&ob[(ko * 3 + 2) * THREADS + tid], rc);

            a = an; d = dn; c = cn;
        }

        // Last voxel block of this batch resets per-batch state for replay.
        __syncthreads();
        if (tid == 0) {
            const unsigned v = atomicAdd(&g_vdone[b], 1u);
            if (v == (unsigned)(M2 - 1)) {
                g_done[b]  = 0u;
                g_vdone[b] = 0u;
                __threadfence();
            }
        }
    }
}

extern "C" void kernel_launch(void* const* d_in, const int* in_sizes, int n_in,
                              void* d_out, int out_size) {
    const float4* p = (const float4*)d_in[0];
    float4* o = (float4*)d_out;
    fused_pipeline_kernel<<<NB * PER_B, THREADS>>>(p, o);
}

// round 10
// speedup vs baseline: 1.0535x; 1.0535x over previous
#include <cuda_runtime.h>
#include <cfloat>

// Problem shape (fixed by reference): point_cloud [32, 262144, 3] fp32
static constexpr int NB       = 32;
static constexpr int NPTS     = 262144;
static constexpr int F_PER_B  = NPTS * 3;            // 786432 floats per batch
static constexpr int Q_PER_B  = F_PER_B / 4;         // 196608 float4 per batch

static constexpr int THREADS  = 256;
static constexpr int G        = 768;                 // single wave: occ>=6 -> 888 slots >= 768

static constexpr int PCH_PER_B = 32;                 // producer chunks per batch
static constexpr int N_PCH     = NB * PCH_PER_B;     // 1024
static constexpr int CHUNK1    = Q_PER_B / PCH_PER_B;    // 6144 float4
static constexpr int ITER1     = CHUNK1 / (3 * THREADS); // 8

static constexpr int CCH_PER_B = 64;                 // consumer chunks per batch
static constexpr int N_CCH     = NB * CCH_PER_B;     // 2048
static constexpr int CHUNK2    = Q_PER_B / CCH_PER_B;    // 3072 float4
static constexpr int ITER2     = CHUNK2 / (3 * THREADS); // 4

// Persistent state — zero-initialized; per-batch counters reset by the last
// consumer of that batch each launch -> graph-replay safe, no init kernel.
__device__ float    g_part[NB][6][PCH_PER_B];  // 0..2 min(x,y,z), 3..5 max
__device__ unsigned g_done[NB];                // producer chunks completed
__device__ unsigned g_vdone[NB];               // consumer chunks completed

// Component bookkeeping: float4 at index idx has components
// ((idx)%3,(idx+1)%3,(idx+2)%3,(idx)%3). All chunk bases are multiples of 3
// and the iteration stride THREADS=256 ≡ 1 (mod 3), so with r = tid%3 the
// float4 at unrolled sub-iter u has leading component (r+u)%3; selection is
// static after pre-rotating accumulators/constants by r.

__device__ __forceinline__ void produce(const float4* __restrict__ p, int cp,
                                        int tid, int r, float (*sh)[THREADS / 32]) {
    const int b = cp >> 5;          // / PCH_PER_B
    const int s = cp & 31;
    const float4* pb = p + (size_t)b * Q_PER_B + (size_t)s * CHUNK1;

    float mnA0 =  FLT_MAX, mnA1 =  FLT_MAX, mnA2 =  FLT_MAX;
    float mxA0 = -FLT_MAX, mxA1 = -FLT_MAX, mxA2 = -FLT_MAX;

    #pragma unroll 4
    for (int ko = 0; ko < ITER1; ko++) {
        const float4 a = pb[(ko * 3 + 0) * THREADS + tid];  // default policy: warms L2 for consumer
        const float4 d = pb[(ko * 3 + 1) * THREADS + tid];
        const float4 c = pb[(ko * 3 + 2) * THREADS + tid];
        mnA0 = fminf(mnA0, fminf(a.x, a.w)); mxA0 = fmaxf(mxA0, fmaxf(a.x, a.w));
        mnA1 = fminf(mnA1, a.y);             mxA1 = fmaxf(mxA1, a.y);
        mnA2 = fminf(mnA2, a.z);             mxA2 = fmaxf(mxA2, a.z);
        mnA1 = fminf(mnA1, fminf(d.x, d.w)); mxA1 = fmaxf(mxA1, fmaxf(d.x, d.w));
        mnA2 = fminf(mnA2, d.y);             mxA2 = fmaxf(mxA2, d.y);
        mnA0 = fminf(mnA0, d.z);             mxA0 = fmaxf(mxA0, d.z);
        mnA2 = fminf(mnA2, fminf(c.x, c.w)); mxA2 = fmaxf(mxA2, fmaxf(c.x, c.w));
        mnA0 = fminf(mnA0, c.y);             mxA0 = fmaxf(mxA0, c.y);
        mnA1 = fminf(mnA1, c.z);             mxA1 = fmaxf(mxA1, c.z);
    }

    // Un-rotate: comp k lives in slot (k - r + 3) % 3
    float mn0, mn1, mn2, mx0, mx1, mx2;
    if (r == 0)      { mn0 = mnA0; mn1 = mnA1; mn2 = mnA2; mx0 = mxA0; mx1 = mxA1; mx2 = mxA2; }
    else if (r == 1) { mn0 = mnA2; mn1 = mnA0; mn2 = mnA1; mx0 = mxA2; mx1 = mxA0; mx2 = mxA1; }
    else             { mn0 = mnA1; mn1 = mnA2; mn2 = mnA0; mx0 = mxA1; mx1 = mxA2; mx2 = mxA0; }

    #pragma unroll
    for (int off = 16; off > 0; off >>= 1) {
        mn0 = fminf(mn0, __shfl_xor_sync(0xFFFFFFFFu, mn0, off));
        mn1 = fminf(mn1, __shfl_xor_sync(0xFFFFFFFFu, mn1, off));
        mn2 = fminf(mn2, __shfl_xor_sync(0xFFFFFFFFu, mn2, off));
        mx0 = fmaxf(mx0, __shfl_xor_sync(0xFFFFFFFFu, mx0, off));
        mx1 = fmaxf(mx1, __shfl_xor_sync(0xFFFFFFFFu, mx1, off));
        mx2 = fmaxf(mx2, __shfl_xor_sync(0xFFFFFFFFu, mx2, off));
    }

    const int w = tid >> 5, lane = tid & 31;
    __syncthreads();                        // protect shared reuse across calls
    if (lane == 0) {
        sh[0][w] = mn0; sh[1][w] = mn1; sh[2][w] = mn2;
        sh[3][w] = mx0; sh[4][w] = mx1; sh[5][w] = mx2;
    }
    __syncthreads();

    if (tid < 6) {
        float v = sh[tid][0];
        if (tid < 3) {
            #pragma unroll
            for (int k = 1; k < THREADS / 32; k++) v = fminf(v, sh[tid][k]);
        } else {
            #pragma unroll
            for (int k = 1; k < THREADS / 32; k++) v = fmaxf(v, sh[tid][k]);
        }
        g_part[b][tid][s] = v;
    }
    __syncthreads();
    if (tid == 0) {
        __threadfence();                    // publish partials before signal
        atomicAdd(&g_done[b], 1u);          // release
    }
}

__device__ __forceinline__ void consume(const float4* __restrict__ p,
                                        float4* __restrict__ out, int cc,
                                        int tid, int r, float* cst) {
    const int b = cc >> 6;          // / CCH_PER_B
    const int s = cc & 63;

    // Wait until all 32 producer chunks of batch b have signalled.
    if (tid == 0) {
        while (__ldcg((const unsigned*)&g_done[b]) < (unsigned)PCH_PER_B)
            __nanosleep(64);
        __threadfence();                    // acquire
    }
    __syncthreads();

    // Reduce the 32 partials: warps 0..5, one quantity each (L2 reads).
    {
        const int w = tid >> 5, lane = tid & 31;
        if (w < 6) {
            float v = __ldcg(&g_part[b][w][lane]);
            if (w < 3) {
                #pragma unroll
                for (int off = 16; off > 0; off >>= 1)
                    v = fminf(v, __shfl_xor_sync(0xFFFFFFFFu, v, off));
            } else {
                #pragma unroll
                for (int off = 16; off > 0; off >>= 1)
                    v = fmaxf(v, __shfl_xor_sync(0xFFFFFFFFu, v, off));
            }
            if (lane == 0) cst[w] = v;
        }
    }
    __syncthreads();

    // Same RN /40 as reference, then reciprocal-multiply per point.
    const float mnc[3]  = { cst[0], cst[1], cst[2] };
    const float invc[3] = { 1.0f / ((cst[3] - cst[0]) / 40.0f),
                            1.0f / ((cst[4] - cst[1]) / 40.0f),
                            1.0f / ((cst[5] - cst[2]) / 40.0f) };
    const float mn_0 = mnc[r], mn_1 = mnc[(r + 1) % 3], mn_2 = mnc[(r + 2) % 3];
    const float iv_0 = invc[r], iv_1 = invc[(r + 1) % 3], iv_2 = invc[(r + 2) % 3];

    const size_t base = (size_t)b * Q_PER_B + (size_t)s * CHUNK2;
    const float4* pb = p + base;
    float4* ob = out + base;

    #pragma unroll 2
    for (int ko = 0; ko < ITER2; ko++) {
        const float4 a = __ldcs(&pb[(ko * 3 + 0) * THREADS + tid]);  // expect L2-hot
        const float4 d = __ldcs(&pb[(ko * 3 + 1) * THREADS + tid]);
        const float4 c = __ldcs(&pb[(ko * 3 + 2) * THREADS + tid]);

        float4 ra, rd, rc;
        // u=0: comps (0,1,2,0) after rotation
        ra.x = floorf((a.x - mn_0) * iv_0);
        ra.y = floorf((a.y - mn_1) * iv_1);
        ra.z = floorf((a.z - mn_2) * iv_2);
        ra.w = floorf((a.w - mn_0) * iv_0);
        // u=1: comps (1,2,0,1)
        rd.x = floorf((d.x - mn_1) * iv_1);
        rd.y = floorf((d.y - mn_2) * iv_2);
        rd.z = floorf((d.z - mn_0) * iv_0);
        rd.w = floorf((d.w - mn_1) * iv_1);
        // u=2: comps (2,0,1,2)
        rc.x = floorf((c.x - mn_2) * iv_2);
        rc.y = floorf((c.y - mn_0) * iv_0);
        rc.z = floorf((c.z - mn_1) * iv_1);
        rc.w = floorf((c.w - mn_2) * iv_2);

        __stcs(&ob[(ko * 3 + 0) * THREADS + tid], ra);
        __stcs(&ob[(ko * 3 + 1) * THREADS + tid], rd);
        __stcs(&ob[(ko * 3 + 2) * THREADS + tid], rc);
    }

    // Last consumer of this batch resets its counters for the next replay.
    __syncthreads();
    if (tid == 0) {
        const unsigned v = atomicAdd(&g_vdone[b], 1u);
        if (v == (unsigned)(CCH_PER_B - 1)) {
            g_done[b]  = 0u;
            g_vdone[b] = 0u;
            __threadfence();
        }
    }
}

// Every block: produce first (1-2 chunks), then consume (2-3 chunks).
// Producer chunks: block k -> {k} ∪ {k+768 if k<256}        (covers 0..1023)
// Consumer chunks: block k -> {767-k, 1535-k} ∪ {2303-k if k>=256} (covers 0..2047)
// Reverse consumer mapping complements the producer load (2p+2c or 1p+3c) and
// aligns consumer batches with producer finish times (increasing ready-order).
__global__ void __launch_bounds__(THREADS, 6)
pipeline_kernel(const float4* __restrict__ p, float4* __restrict__ out) {
    const int k   = blockIdx.x;
    const int tid = threadIdx.x;
    const int r   = tid % 3;

    __shared__ float sh[6][THREADS / 32];

    produce(p, k, tid, r, sh);
    if (k < N_PCH - G) produce(p, k + G, tid, r, sh);   // k < 256

    consume(p, out, (G - 1) - k,        tid, r, &sh[0][0]);
    consume(p, out, (G - 1) - k + G,    tid, r, &sh[0][0]);
    if (k >= N_PCH - G)                                  // k >= 256
        consume(p, out, (G - 1) - k + 2 * G, tid, r, &sh[0][0]);
}

extern "C" void kernel_launch(void* const* d_in, const int* in_sizes, int n_in,
                              void* d_out, int out_size) {
    const float4* p = (const float4*)d_in[0];
    float4* o = (float4*)d_out;
    pipeline_kernel<<<G, THREADS>>>(p, o);
}